// round 7
// baseline (speedup 1.0000x reference)
#include <cuda_runtime.h>
#include <cstdint>

#define T_STEPS 20
#define HID     128
#define BATCH   65536
#define M_TILE  64
#define THREADS 256
#define HPAD    68            // padded m-stride of transposed h buffer
#define HBUF    (128 * HPAD)  // 8704 floats per h buffer

// Shared memory layout (floats)
#define OFF_W    0
#define OFF_H    (OFF_W + 2 * 16384)          // 32768
#define OFF_OBS  (OFF_H + 2 * HBUF)           // 32768 + 17408 = 50176
#define OFF_WC   (OFF_OBS + T_STEPS * 128)    // 50176 + 2560 = 52736
#define OFF_BC   (OFF_WC + 1024)              // 53760
#define SMEM_FLOATS (OFF_BC + 512)            // 54272
#define SMEM_BYTES  (SMEM_FLOATS * 4)         // 217088 bytes

// Precomputed weights (device scratch; no runtime allocation allowed)
__device__ __align__(16) float g_Wt[4][128][128]; // [gate][k][d] = W_hh[(g*128+d)*128+k]
__device__ __align__(16) float g_Wc[2][512];      // combined obs->gate weights
__device__ __align__(16) float g_bc[512];         // combined bias

typedef unsigned long long u64t;

__device__ __forceinline__ u64t fma2(u64t a, u64t b, u64t c) {
    u64t d;
    asm("fma.rn.f32x2 %0, %1, %2, %3;" : "=l"(d) : "l"(a), "l"(b), "l"(c));
    return d;
}
__device__ __forceinline__ u64t pack2(float x) {
    u64t d;
    asm("mov.b64 %0, {%1, %1};" : "=l"(d) : "f"(x));
    return d;
}
__device__ __forceinline__ void unpack2(u64t v, float& lo, float& hi) {
    asm("mov.b64 {%0, %1}, %2;" : "=f"(lo), "=f"(hi) : "l"(v));
}

__device__ __forceinline__ void cp16(void* dst_smem, const void* src) {
    uint32_t d = (uint32_t)__cvta_generic_to_shared(dst_smem);
    asm volatile("cp.async.cg.shared.global [%0], [%1], 16;" :: "r"(d), "l"(src));
}
#define CP_COMMIT() asm volatile("cp.async.commit_group;" ::: "memory")
#define CP_WAIT1()  asm volatile("cp.async.wait_group 1;"  ::: "memory")
#define CP_WAIT0()  asm volatile("cp.async.wait_group 0;"  ::: "memory")

__device__ __forceinline__ float fsig(float x) {
    // sigmoid via EX2 + RCP approx: rel err ~1e-6, far inside 1e-3 budget
    float e = __expf(-x);
    return __fdividef(1.0f, 1.0f + e);
}
__device__ __forceinline__ float ftanh(float x) {
    x = fminf(fmaxf(x, -15.0f), 15.0f);   // keep exp finite; tanh(15)=1-2e-13
    float e = __expf(-2.0f * x);
    return __fdividef(1.0f - e, 1.0f + e);
}

// ---------------------------------------------------------------------------
// Setup: fold embedding into gate weights; transpose W_hh per gate (k-major).
// ---------------------------------------------------------------------------
__global__ void setup_kernel(const float* __restrict__ W_emb, const float* __restrict__ b_emb,
                             const float* __restrict__ W_ih,  const float* __restrict__ W_hh,
                             const float* __restrict__ b_ih,  const float* __restrict__ b_hh) {
    int gid = blockIdx.x * blockDim.x + threadIdx.x;
    if (gid < 4 * 128 * 128) {
        int g = gid >> 14;
        int k = (gid >> 7) & 127;
        int d = gid & 127;
        g_Wt[g][k][d] = W_hh[(g * 128 + d) * 128 + k];
    }
    if (gid < 512) {
        float w0 = 0.f, w1 = 0.f, bb = 0.f;
        #pragma unroll 8
        for (int j = 0; j < 64; ++j) {
            float wij = W_ih[gid * 64 + j];
            w0 += wij * W_emb[j * 2 + 0];
            w1 += wij * W_emb[j * 2 + 1];
            bb += wij * b_emb[j];
        }
        g_Wc[0][gid] = w0;
        g_Wc[1][gid] = w1;
        g_bc[gid]    = bb + b_ih[gid] + b_hh[gid];
    }
}

// ---------------------------------------------------------------------------
// Main fused LSTM kernel.
// Block: 64 batch rows, 256 threads = 32 tx (d-groups of 4) x 8 ty (m-groups of 8).
// h ping-pongs in smem transposed [k][m]; c in registers; gates accumulated in
// packed f32x2 registers; weights double-buffered via cp.async from L2.
// ---------------------------------------------------------------------------
__global__ void __launch_bounds__(THREADS, 1)
lstm_kernel(const float* __restrict__ obs, const float* __restrict__ h0,
            const float* __restrict__ c0, float* __restrict__ out) {
    extern __shared__ float smem[];
    float* sW   = smem + OFF_W;    // 2 x [128][128]  gate-chunk weights, k-major
    float* sH   = smem + OFF_H;    // 2 x [128][HPAD] transposed hidden state
    float* sObs = smem + OFF_OBS;  // [20][64][2]
    float* sWc  = smem + OFF_WC;   // [2][512]
    float* sBc  = smem + OFF_BC;   // [512]

    const int tid   = threadIdx.x;
    const int tx    = tid & 31;        // d-group: d in [4*tx, 4*tx+4)
    const int ty    = tid >> 5;        // m-group: m in [8*ty, 8*ty+8)
    const int mLoc  = 8 * ty;
    const int mBase = blockIdx.x * M_TILE;

    // --- Stage h0 (transposed), obs slab, combined weights/bias ---
    for (int idx = tid; idx < M_TILE * HID; idx += THREADS) {
        int m = idx >> 7, d = idx & 127;
        sH[d * HPAD + m] = h0[(size_t)(mBase + m) * HID + d];
    }
    for (int idx = tid; idx < T_STEPS * M_TILE * 2; idx += THREADS) {
        int t = idx >> 7, r = idx & 127;
        sObs[idx] = obs[(size_t)t * BATCH * 2 + (size_t)mBase * 2 + r];
    }
    for (int idx = tid; idx < 1024; idx += THREADS) sWc[idx] = (&g_Wc[0][0])[idx];
    // BUGFIX (R4): 512 bias entries with only 256 threads — must stride.
    // The old `if (tid < 512)` left sBc[256..511] (g and o gate biases)
    // uninitialized, which was the entire rel_err=0.84 failure.
    for (int idx = tid; idx < 512; idx += THREADS) sBc[idx] = g_bc[idx];

    // --- c0 into registers: cc[mi][j], j -> d = 4*tx + j ---
    float cc[8][4];
    #pragma unroll
    for (int mi = 0; mi < 8; ++mi) {
        float4 a = *(const float4*)&c0[(size_t)(mBase + mLoc + mi) * HID + 4 * tx];
        cc[mi][0] = a.x; cc[mi][1] = a.y; cc[mi][2] = a.z; cc[mi][3] = a.w;
    }

    // --- Prefetch gate chunk 0 into weight buffer 0 ---
    {
        const float4* src = (const float4*)&g_Wt[0][0][0];
        float* dst = sW;
        #pragma unroll
        for (int i = 0; i < 16; ++i)
            cp16(dst + (tid + i * 256) * 4, src + tid + i * 256);
        CP_COMMIT();
    }
    __syncthreads();   // staging visible to all threads

    int hcur = 0;
    u64t acc[4][8][2]; // [gate][mi][pair]  (pair0: d=4tx..4tx+1, pair1: 4tx+2..4tx+3)

    for (int t = 0; t < T_STEPS; ++t) {
        // --- init gates with combined bias + obs contribution ---
        u64t op0[8], op1[8];
        #pragma unroll
        for (int mi = 0; mi < 8; ++mi) {
            float2 ov = *(const float2*)&sObs[t * 128 + (mLoc + mi) * 2];
            op0[mi] = pack2(ov.x);
            op1[mi] = pack2(ov.y);
        }
        #pragma unroll
        for (int g = 0; g < 4; ++g) {
            int n = g * 128 + 4 * tx;
            u64t b0  = *(const u64t*)&sBc[n];
            u64t b1  = *(const u64t*)&sBc[n + 2];
            u64t wA0 = *(const u64t*)&sWc[n];
            u64t wA1 = *(const u64t*)&sWc[n + 2];
            u64t wB0 = *(const u64t*)&sWc[512 + n];
            u64t wB1 = *(const u64t*)&sWc[512 + n + 2];
            #pragma unroll
            for (int mi = 0; mi < 8; ++mi) {
                acc[g][mi][0] = fma2(op1[mi], wB0, fma2(op0[mi], wA0, b0));
                acc[g][mi][1] = fma2(op1[mi], wB1, fma2(op0[mi], wA1, b1));
            }
        }

        // --- recurrent GEMM: 4 gate chunks, K=128, cp.async double buffered ---
        #pragma unroll
        for (int g = 0; g < 4; ++g) {
            __syncthreads();   // prior chunk's reads done; h writes (prev step) visible
            {
                const float4* src = (const float4*)&g_Wt[(g + 1) & 3][0][0];
                float* dst = sW + ((g + 1) & 1) * 16384;
                #pragma unroll
                for (int i = 0; i < 16; ++i)
                    cp16(dst + (tid + i * 256) * 4, src + tid + i * 256);
                CP_COMMIT();
                CP_WAIT1();    // current chunk's group complete (own thread)
            }
            __syncthreads();   // all threads' cp.async for current chunk visible

            const float* wb = sW + (g & 1) * 16384;
            const float* hb = sH + hcur * HBUF + mLoc;
            #pragma unroll 8
            for (int k = 0; k < 128; ++k) {
                float4 hA = *(const float4*)(hb + k * HPAD);       // h[k][m..m+3] (broadcast)
                float4 hB = *(const float4*)(hb + k * HPAD + 4);   // h[k][m+4..m+7]
                ulonglong2 wv = *(const ulonglong2*)(wb + k * 128 + 4 * tx);
                u64t hp0 = pack2(hA.x), hp1 = pack2(hA.y), hp2 = pack2(hA.z), hp3 = pack2(hA.w);
                u64t hp4 = pack2(hB.x), hp5 = pack2(hB.y), hp6 = pack2(hB.z), hp7 = pack2(hB.w);
                acc[g][0][0] = fma2(hp0, wv.x, acc[g][0][0]); acc[g][0][1] = fma2(hp0, wv.y, acc[g][0][1]);
                acc[g][1][0] = fma2(hp1, wv.x, acc[g][1][0]); acc[g][1][1] = fma2(hp1, wv.y, acc[g][1][1]);
                acc[g][2][0] = fma2(hp2, wv.x, acc[g][2][0]); acc[g][2][1] = fma2(hp2, wv.y, acc[g][2][1]);
                acc[g][3][0] = fma2(hp3, wv.x, acc[g][3][0]); acc[g][3][1] = fma2(hp3, wv.y, acc[g][3][1]);
                acc[g][4][0] = fma2(hp4, wv.x, acc[g][4][0]); acc[g][4][1] = fma2(hp4, wv.y, acc[g][4][1]);
                acc[g][5][0] = fma2(hp5, wv.x, acc[g][5][0]); acc[g][5][1] = fma2(hp5, wv.y, acc[g][5][1]);
                acc[g][6][0] = fma2(hp6, wv.x, acc[g][6][0]); acc[g][6][1] = fma2(hp6, wv.y, acc[g][6][1]);
                acc[g][7][0] = fma2(hp7, wv.x, acc[g][7][0]); acc[g][7][1] = fma2(hp7, wv.y, acc[g][7][1]);
            }
        }

        // --- elementwise LSTM update; write h_new into the other buffer ---
        int hnxt = hcur ^ 1;
        float* hw = sH + hnxt * HBUF;
        #pragma unroll
        for (int mi = 0; mi < 8; ++mi) {
            int m = mLoc + mi;
            #pragma unroll
            for (int p = 0; p < 2; ++p) {
                float ia, ib, fa, fb, ga, gb, oa, ob;
                unpack2(acc[0][mi][p], ia, ib);
                unpack2(acc[1][mi][p], fa, fb);
                unpack2(acc[2][mi][p], ga, gb);
                unpack2(acc[3][mi][p], oa, ob);
                int d  = 4 * tx + 2 * p;
                int ci = 2 * p;
                {
                    float cv = cc[mi][ci];
                    float cn = fsig(fa) * cv + fsig(ia) * ftanh(ga);
                    cc[mi][ci] = cn;
                    hw[d * HPAD + m] = fsig(oa) * ftanh(cn);
                }
                {
                    float cv = cc[mi][ci + 1];
                    float cn = fsig(fb) * cv + fsig(ib) * ftanh(gb);
                    cc[mi][ci + 1] = cn;
                    hw[(d + 1) * HPAD + m] = fsig(ob) * ftanh(cn);
                }
            }
        }
        hcur = hnxt;
        // next iteration's first __syncthreads orders these writes before reads
    }

    CP_WAIT0();
    __syncthreads();

    // --- write final h (coalesced along d) ---
    const float* hf = sH + hcur * HBUF;
    for (int idx = tid; idx < M_TILE * HID; idx += THREADS) {
        int m = idx >> 7, d = idx & 127;
        out[(size_t)(mBase + m) * HID + d] = hf[d * HPAD + m];
    }
}

extern "C" void kernel_launch(void* const* d_in, const int* in_sizes, int n_in,
                              void* d_out, int out_size) {
    const float* obs   = (const float*)d_in[0];
    const float* h0    = (const float*)d_in[1];
    const float* c0    = (const float*)d_in[2];
    const float* W_emb = (const float*)d_in[3];
    const float* b_emb = (const float*)d_in[4];
    const float* W_ih  = (const float*)d_in[5];
    const float* W_hh  = (const float*)d_in[6];
    const float* b_ih  = (const float*)d_in[7];
    const float* b_hh  = (const float*)d_in[8];
    float* out = (float*)d_out;

    (void)in_sizes; (void)n_in; (void)out_size;

    setup_kernel<<<256, 256>>>(W_emb, b_emb, W_ih, W_hh, b_ih, b_hh);

    cudaFuncSetAttribute(lstm_kernel, cudaFuncAttributeMaxDynamicSharedMemorySize, SMEM_BYTES);
    lstm_kernel<<<BATCH / M_TILE, THREADS, SMEM_BYTES>>>(obs, h0, c0, out);
}